// round 2
// baseline (speedup 1.0000x reference)
#include <cuda_runtime.h>
#include <math.h>

#define B_      2
#define T_      2048
#define D_      2048
#define NH_     8
#define NKV_    4
#define HD_     256
#define SC_     2048
#define WIN_    512
#define SOFTCAP 50.0f
#define NEGINF  -2.3819763e38f

// ---------------- scratch (device globals; no allocation allowed) ------------
__device__ float g_q[(size_t)B_*T_*NH_*HD_];      // 33.5 MB
__device__ float g_k[(size_t)B_*T_*NKV_*HD_];     // 16.8 MB (pre-rope)
__device__ float g_v[(size_t)B_*T_*NKV_*HD_];     // 16.8 MB
__device__ float g_kc[(size_t)B_*SC_*NKV_*HD_];   // merged K cache
__device__ float g_vc[(size_t)B_*SC_*NKV_*HD_];   // merged V cache
__device__ float g_attn[(size_t)B_*T_*NH_*HD_];   // attention output

// ---------------- SGEMM: C[M,N] = A[M,K] @ W[K,N], all row-major, fp32 -------
// 128x128 block tile, BK=8, 8x8 per-thread microtile, 256 threads.
__global__ void __launch_bounds__(256) sgemm128(const float* __restrict__ A,
                                                const float* __restrict__ W,
                                                float* __restrict__ C,
                                                int M, int N, int K)
{
    __shared__ float As[8][128];   // transposed A tile
    __shared__ float Bs[8][128];

    const int tid = threadIdx.x;
    const int row0 = blockIdx.y * 128;
    const int col0 = blockIdx.x * 128;

    const float* Ab = A + (size_t)row0 * K;
    const float* Wb = W + col0;

    const int arow = tid >> 1;             // 0..127
    const int acol = (tid & 1) * 4;        // 0 or 4
    const int brow = tid >> 5;             // 0..7
    const int bcol = (tid & 31) * 4;       // 0..124

    const int tr = (tid >> 4) * 8;         // 0..120
    const int tc = (tid & 15) * 8;

    float acc[8][8];
#pragma unroll
    for (int i = 0; i < 8; i++)
#pragma unroll
        for (int j = 0; j < 8; j++) acc[i][j] = 0.0f;

    for (int k0 = 0; k0 < K; k0 += 8) {
        float4 av = *(const float4*)(Ab + (size_t)arow * K + k0 + acol);
        As[acol + 0][arow] = av.x;
        As[acol + 1][arow] = av.y;
        As[acol + 2][arow] = av.z;
        As[acol + 3][arow] = av.w;
        float4 bv = *(const float4*)(Wb + (size_t)(k0 + brow) * N + bcol);
        *(float4*)&Bs[brow][bcol] = bv;
        __syncthreads();

#pragma unroll
        for (int kk = 0; kk < 8; kk++) {
            float ra[8], rb[8];
#pragma unroll
            for (int i = 0; i < 8; i++) ra[i] = As[kk][tr + i];
#pragma unroll
            for (int j = 0; j < 8; j++) rb[j] = Bs[kk][tc + j];
#pragma unroll
            for (int i = 0; i < 8; i++)
#pragma unroll
                for (int j = 0; j < 8; j++) acc[i][j] = fmaf(ra[i], rb[j], acc[i][j]);
        }
        __syncthreads();
    }

#pragma unroll
    for (int i = 0; i < 8; i++) {
        float* crow = C + (size_t)(row0 + tr + i) * N + col0 + tc;
#pragma unroll
        for (int j = 0; j < 8; j += 4) {
            float4 v = make_float4(acc[i][j], acc[i][j+1], acc[i][j+2], acc[i][j+3]);
            *(float4*)(crow + j) = v;
        }
    }
}

// ---------------- cache merge: scratch caches = input caches (+ V slice) -----
__global__ void merge_cache(const float* __restrict__ kcache,
                            const float* __restrict__ vcache,
                            const int* __restrict__ cur)
{
    const int idx = blockIdx.x * 256 + threadIdx.x;   // < B*SC*NKV*HD = 4.19M
    const int per_b = SC_ * NKV_ * HD_;
    const int b = idx / per_b;
    const int rem = idx - b * per_b;
    const int s = rem / (NKV_ * HD_);
    const int c = rem - s * (NKV_ * HD_);
    const int ci = *cur;
    const int t = s - ci;
    g_kc[idx] = kcache[idx];   // K slice overwritten later by normrope_k
    g_vc[idx] = (t >= 0 && t < T_) ? g_v[((size_t)b * T_ + t) * (NKV_ * HD_) + c]
                                   : vcache[idx];
}

// ---------------- RMSNorm + RoPE ---------------------------------------------
// One block per (b*t, head); 256 threads = head dims.
// to_cache=1: write k into g_kc at slot cur+t. to_cache=0: in-place on q.
__global__ void normrope_kernel(const float* __restrict__ in,
                                float* __restrict__ out,
                                const float* __restrict__ scale,
                                const int* __restrict__ seg,
                                const int* __restrict__ cur,
                                int heads, int to_cache)
{
    const int bt = blockIdx.x;
    const int h  = blockIdx.y;
    const int d  = threadIdx.x;

    const float v = in[((size_t)bt * heads + h) * HD_ + d];

    // block sum of squares
    float ss = v * v;
#pragma unroll
    for (int o = 16; o; o >>= 1) ss += __shfl_xor_sync(0xffffffffu, ss, o);
    __shared__ float red[8];
    __shared__ float s_ms;
    __shared__ float sh[HD_];
    const int lane = d & 31, w = d >> 5;
    if (lane == 0) red[w] = ss;
    __syncthreads();
    if (d == 0) {
        float t = 0.0f;
#pragma unroll
        for (int i = 0; i < 8; i++) t += red[i];
        s_ms = rsqrtf(t / (float)HD_ + 1e-6f);
    }
    __syncthreads();

    const float n = v * s_ms * (1.0f + scale[d]);
    sh[d] = n;
    __syncthreads();

    const int pos = seg[bt];
    const int i = d & 127;
    // double-precision trig: immune to fast-math range issues (angles up to ~2047)
    const double ts  = pow(10000.0, (double)i / 128.0);
    const double ang = (double)pos / ts;
    double sn, cs;
    sincos(ang, &sn, &cs);
    const float x1 = sh[i], x2 = sh[i + 128];
    const float r = (d < 128) ? (float)((double)x1 * cs - (double)x2 * sn)
                              : (float)((double)x2 * cs + (double)x1 * sn);

    if (to_cache) {
        const int b = bt / T_, t = bt - b * T_;
        const int slot = *cur + t;
        if (slot < SC_)
            out[(((size_t)b * SC_ + slot) * heads + h) * HD_ + d] = r;
    } else {
        out[((size_t)bt * heads + h) * HD_ + d] = r;
    }
}

// ---------------- windowed flash attention -----------------------------------
// Block handles (b, head, 32-query tile). 256 threads.
// Shared rows padded to 260 floats (bank-conflict-free dots).
struct AttnSmem {
    float Qs[32 * 260];
    float Ks[32 * 260];
    float Vs[32 * 260];
    float Ss[32 * 33];
    float m[32], l[32], al[32];
    int   pos[32];
    int   srange[2];
};

__global__ void __launch_bounds__(256) attn_kernel(const int* __restrict__ seg)
{
    extern __shared__ char smem_raw[];
    AttnSmem& sm = *reinterpret_cast<AttnSmem*>(smem_raw);

    const int tid = threadIdx.x;
    const int q0  = blockIdx.x * 32;
    const int h   = blockIdx.y;
    const int b   = blockIdx.z;
    const int kv  = h / (NH_ / NKV_);

    // ---- load Q tile (pre-scaled by HD^-0.5) ----
    const float* qbase = g_q + (((size_t)b * T_ + q0) * NH_ + h) * HD_;
    const float qscale = 0.0625f;  // 1/sqrt(256)
#pragma unroll
    for (int j = 0; j < 8; j++) {
        const int fi = tid + j * 256;          // float4 index over 32x64
        const int r = fi >> 6, c4 = fi & 63;
        float4 v = *(const float4*)(qbase + (size_t)r * NH_ * HD_ + c4 * 4);
        float* dst = &sm.Qs[r * 260 + c4 * 4];
        dst[0] = v.x * qscale; dst[1] = v.y * qscale;
        dst[2] = v.z * qscale; dst[3] = v.w * qscale;
    }
    if (tid < 32) {
        sm.m[tid] = -1e30f;
        sm.l[tid] = 0.0f;
        sm.pos[tid] = seg[b * T_ + q0 + tid];
    }
    __syncthreads();
    if (tid == 0) {
        int mn = sm.pos[0], mx = sm.pos[0];
        for (int j = 1; j < 32; j++) { mn = min(mn, sm.pos[j]); mx = max(mx, sm.pos[j]); }
        int lo = mn - (WIN_ - 1); if (lo < 0) lo = 0;
        int hi = mx; if (hi > SC_ - 1) hi = SC_ - 1;
        sm.srange[0] = lo & ~31;
        sm.srange[1] = hi;
    }
    __syncthreads();
    const int s_lo = sm.srange[0], s_hi = sm.srange[1];

    float4 o4[8];
#pragma unroll
    for (int j = 0; j < 8; j++) o4[j] = make_float4(0.f, 0.f, 0.f, 0.f);
    const int r_acc = tid & 31;        // query row owned in accumulation phase
    const int dg    = tid >> 5;        // dim group (32 dims)

    const float* kbase = g_kc + ((size_t)b * SC_ * NKV_ + kv) * HD_;
    const float* vbase = g_vc + ((size_t)b * SC_ * NKV_ + kv) * HD_;

    for (int s0 = s_lo; s0 <= s_hi; s0 += 32) {
        // ---- load K/V tiles ----
#pragma unroll
        for (int j = 0; j < 8; j++) {
            const int fi = tid + j * 256;
            const int r = fi >> 6, c4 = fi & 63;
            const int s = s0 + r;
            float4 kvv = make_float4(0.f,0.f,0.f,0.f), vvv = kvv;
            if (s < SC_) {
                kvv = *(const float4*)(kbase + (size_t)s * NKV_ * HD_ + c4 * 4);
                vvv = *(const float4*)(vbase + (size_t)s * NKV_ * HD_ + c4 * 4);
            }
            float* kd = &sm.Ks[r * 260 + c4 * 4];
            kd[0] = kvv.x; kd[1] = kvv.y; kd[2] = kvv.z; kd[3] = kvv.w;
            float* vd = &sm.Vs[r * 260 + c4 * 4];
            vd[0] = vvv.x; vd[1] = vvv.y; vd[2] = vvv.z; vd[3] = vvv.w;
        }
        __syncthreads();

        // ---- scores: thread (qr, gi) does 4 keys gi+8i ----
        {
            const int qr = tid >> 3, gi = tid & 7;
            float acc[4] = {0.f, 0.f, 0.f, 0.f};
            const float* qrow = &sm.Qs[qr * 260];
            for (int d4 = 0; d4 < 64; d4++) {
                const float4 qv = *(const float4*)&qrow[d4 * 4];
#pragma unroll
                for (int i = 0; i < 4; i++) {
                    const float4 kvv = *(const float4*)&sm.Ks[(gi + 8*i) * 260 + d4 * 4];
                    acc[i] += qv.x*kvv.x + qv.y*kvv.y + qv.z*kvv.z + qv.w*kvv.w;
                }
            }
            const int qp = sm.pos[qr];
#pragma unroll
            for (int i = 0; i < 4; i++) {
                const int sj = gi + 8*i;
                const int s  = s0 + sj;
                const float sv = SOFTCAP * tanhf(acc[i] * (1.0f / SOFTCAP));
                const bool valid = (s <= qp) && (qp - s < WIN_) && (s < SC_);
                sm.Ss[qr * 33 + sj] = valid ? sv : NEGINF;
            }
        }
        __syncthreads();

        // ---- per-row online-softmax stats ----
        if (tid < 32) {
            const int r = tid;
            const float mo = sm.m[r];
            float mx = mo;
            for (int j = 0; j < 32; j++) mx = fmaxf(mx, sm.Ss[r * 33 + j]);
            const float a = expf(mo - mx);
            float ls = sm.l[r] * a;
            for (int j = 0; j < 32; j++) {
                const float p = expf(sm.Ss[r * 33 + j] - mx);
                sm.Ss[r * 33 + j] = p;
                ls += p;
            }
            sm.m[r] = mx; sm.l[r] = ls; sm.al[r] = a;
        }
        __syncthreads();

        // ---- accumulate O (thread owns row r_acc, dims dg*32..+31) ----
        {
            const float a = sm.al[r_acc];
#pragma unroll
            for (int j = 0; j < 8; j++) {
                o4[j].x *= a; o4[j].y *= a; o4[j].z *= a; o4[j].w *= a;
            }
            for (int s = 0; s < 32; s++) {
                const float p = sm.Ss[r_acc * 33 + s];
                const float4* vr = (const float4*)&sm.Vs[s * 260 + dg * 32];
#pragma unroll
                for (int j = 0; j < 8; j++) {
                    const float4 vv = vr[j];
                    o4[j].x += p * vv.x; o4[j].y += p * vv.y;
                    o4[j].z += p * vv.z; o4[j].w += p * vv.w;
                }
            }
        }
        __syncthreads();
    }

    const float linv = 1.0f / sm.l[r_acc];
    float* outp = g_attn + (((size_t)b * T_ + q0 + r_acc) * NH_ + h) * HD_ + dg * 32;
#pragma unroll
    for (int j = 0; j < 8; j++) {
        float4 v = o4[j];
        v.x *= linv; v.y *= linv; v.z *= linv; v.w *= linv;
        *(float4*)(outp + j * 4) = v;
    }
}

// ---------------- launcher ----------------------------------------------------
extern "C" void kernel_launch(void* const* d_in, const int* in_sizes, int n_in,
                              void* d_out, int out_size)
{
    const float* x      = (const float*)d_in[0];
    const int*   seg    = (const int*)  d_in[1];
    const int*   cur    = (const int*)  d_in[2];
    const float* wq     = (const float*)d_in[3];
    const float* wk     = (const float*)d_in[4];
    const float* wv     = (const float*)d_in[5];
    const float* wo     = (const float*)d_in[6];
    const float* qns    = (const float*)d_in[7];
    const float* kns    = (const float*)d_in[8];
    const float* kcache = (const float*)d_in[9];
    const float* vcache = (const float*)d_in[10];
    float* out = (float*)d_out;

    float *qp, *kp, *vp, *attnp;
    cudaGetSymbolAddress((void**)&qp,    g_q);
    cudaGetSymbolAddress((void**)&kp,    g_k);
    cudaGetSymbolAddress((void**)&vp,    g_v);
    cudaGetSymbolAddress((void**)&attnp, g_attn);

    const int M = B_ * T_;  // 4096

    // QKV projections
    sgemm128<<<dim3((NH_*HD_)/128,  M/128), 256>>>(x, wq, qp, M, NH_*HD_,  D_);
    sgemm128<<<dim3((NKV_*HD_)/128, M/128), 256>>>(x, wk, kp, M, NKV_*HD_, D_);
    sgemm128<<<dim3((NKV_*HD_)/128, M/128), 256>>>(x, wv, vp, M, NKV_*HD_, D_);

    // merged caches (V slice injected here; K slice written by normrope_k)
    merge_cache<<<(B_*SC_*NKV_*HD_)/256, 256>>>(kcache, vcache, cur);

    // RMSNorm + RoPE
    float *kcp;
    cudaGetSymbolAddress((void**)&kcp, g_kc);
    normrope_kernel<<<dim3(M, NH_),  256>>>(qp, qp,  qns, seg, cur, NH_,  0);
    normrope_kernel<<<dim3(M, NKV_), 256>>>(kp, kcp, kns, seg, cur, NKV_, 1);

    // windowed flash attention
    cudaFuncSetAttribute(attn_kernel, cudaFuncAttributeMaxDynamicSharedMemorySize,
                         (int)sizeof(AttnSmem));
    attn_kernel<<<dim3(T_/32, NH_, B_), 256, sizeof(AttnSmem)>>>(seg);

    // output projection
    sgemm128<<<dim3(D_/128, M/128), 256>>>(attnp, wo, out, M, D_, D_);
}

// round 3
// speedup vs baseline: 3.6558x; 3.6558x over previous
#include <cuda_runtime.h>
#include <math.h>
#include <stdint.h>

#define B_      2
#define T_      2048
#define D_      2048
#define NH_     8
#define NKV_    4
#define HD_     256
#define SC_     2048
#define WIN_    512
#define SOFTCAP 50.0f
#define NEGINF  -2.3819763e38f

// ---------------- scratch (device globals; no allocation allowed) ------------
__device__ float g_q[(size_t)B_*T_*NH_*HD_];      // 33.5 MB
__device__ float g_k[(size_t)B_*T_*NKV_*HD_];     // 16.8 MB (pre-rope)
__device__ float g_v[(size_t)B_*T_*NKV_*HD_];     // 16.8 MB
__device__ float g_kc[(size_t)B_*SC_*NKV_*HD_];   // merged K cache
__device__ float g_vc[(size_t)B_*SC_*NKV_*HD_];   // merged V cache
__device__ float g_attn[(size_t)B_*T_*NH_*HD_];   // attention output
__device__ float2 g_rope[(size_t)SC_*128];        // (cos, sin) per (pos, freq)

// ---------------- tf32 helpers -------------------------------------------------
__device__ __forceinline__ uint32_t f32_to_tf32(float x) {
    uint32_t y;
    asm("cvt.rna.tf32.f32 %0, %1;" : "=r"(y) : "f"(x));
    return y;
}

__device__ __forceinline__ void mma_tf32(float& d0, float& d1, float& d2, float& d3,
                                         uint32_t a0, uint32_t a1, uint32_t a2, uint32_t a3,
                                         uint32_t b0, uint32_t b1) {
    asm volatile("mma.sync.aligned.m16n8k8.row.col.f32.tf32.tf32.f32 "
                 "{%0,%1,%2,%3}, {%4,%5,%6,%7}, {%8,%9}, {%0,%1,%2,%3};"
                 : "+f"(d0), "+f"(d1), "+f"(d2), "+f"(d3)
                 : "r"(a0), "r"(a1), "r"(a2), "r"(a3), "r"(b0), "r"(b1));
}

__device__ __forceinline__ void cpasync16(uint32_t saddr, const void* gptr) {
    asm volatile("cp.async.cg.shared.global [%0], [%1], 16;\n" :: "r"(saddr), "l"(gptr));
}
__device__ __forceinline__ void cpasync_commit() { asm volatile("cp.async.commit_group;"); }
__device__ __forceinline__ void cpasync_wait0()  { asm volatile("cp.async.wait_group 0;"); }
__device__ __forceinline__ void cpasync_wait1()  { asm volatile("cp.async.wait_group 1;"); }

// ---------------- tf32 tensor-core GEMM ----------------------------------------
// C[M,N] = A[M,K] @ W[K,N], row-major fp32 in/out, tf32 mma.
// Block: 128x128, BK=16, 256 threads (8 warps as 2Mx4N, warp tile 64x32).
#define AS_STRIDE 20   // 128 rows x 20 floats (bank-conflict-free frag loads)
#define BS_STRIDE 136  // 16 rows x 136 floats

__global__ void __launch_bounds__(256) gemm_tf32(const float* __restrict__ A,
                                                 const float* __restrict__ W,
                                                 float* __restrict__ C,
                                                 int M, int N, int K)
{
    __shared__ float As[2][128 * AS_STRIDE];
    __shared__ float Bs[2][16 * BS_STRIDE];

    const int tid  = threadIdx.x;
    const int warp = tid >> 5;
    const int lane = tid & 31;
    const int warpM = warp >> 2;     // 0..1
    const int warpN = warp & 3;      // 0..3
    const int gid = lane >> 2;       // 0..7
    const int tig = lane & 3;        // 0..3

    const int row0 = blockIdx.y * 128;
    const int col0 = blockIdx.x * 128;

    // per-thread load coordinates
    const int a_r  = tid >> 2;            // 0..63? no: 0..63 -> need 128 rows; tid>>2 gives 0..63
    // 256 threads, each loads 2 float4 for A: rows t>>2 and (t>>2)+64
    const int a_c4 = (tid & 3) * 4;
    const int b_r  = tid >> 5;            // 0..7 (two iterations: +0, +8)
    const int b_c4 = (tid & 31) * 4;

    uint32_t sA = (uint32_t)__cvta_generic_to_shared(&As[0][0]);
    uint32_t sB = (uint32_t)__cvta_generic_to_shared(&Bs[0][0]);
    const uint32_t sAbuf = 128 * AS_STRIDE * 4;
    const uint32_t sBbuf = 16 * BS_STRIDE * 4;

    const int ntiles = K / 16;

    auto load_tile = [&](int kt, int buf) {
        const float* ag0 = A + (size_t)(row0 + a_r) * K + kt * 16 + a_c4;
        const float* ag1 = A + (size_t)(row0 + a_r + 64) * K + kt * 16 + a_c4;
        cpasync16(sA + buf * sAbuf + (a_r * AS_STRIDE + a_c4) * 4, ag0);
        cpasync16(sA + buf * sAbuf + ((a_r + 64) * AS_STRIDE + a_c4) * 4, ag1);
        const float* bg0 = W + (size_t)(kt * 16 + b_r) * N + col0 + b_c4;
        const float* bg1 = W + (size_t)(kt * 16 + b_r + 8) * N + col0 + b_c4;
        cpasync16(sB + buf * sBbuf + (b_r * BS_STRIDE + b_c4) * 4, bg0);
        cpasync16(sB + buf * sBbuf + ((b_r + 8) * BS_STRIDE + b_c4) * 4, bg1);
    };

    float acc[4][4][4];
#pragma unroll
    for (int i = 0; i < 4; i++)
#pragma unroll
        for (int j = 0; j < 4; j++)
#pragma unroll
            for (int r = 0; r < 4; r++) acc[i][j][r] = 0.0f;

    load_tile(0, 0);
    cpasync_commit();

    for (int kt = 0; kt < ntiles; kt++) {
        const int buf = kt & 1;
        if (kt + 1 < ntiles) {
            load_tile(kt + 1, buf ^ 1);
            cpasync_commit();
            cpasync_wait1();
        } else {
            cpasync_wait0();
        }
        __syncthreads();

        const float* Ab = &As[buf][0];
        const float* Bb = &Bs[buf][0];

#pragma unroll
        for (int ks = 0; ks < 2; ks++) {
            const int kb = ks * 8;
            uint32_t af[4][4], bf[4][2];
#pragma unroll
            for (int mt = 0; mt < 4; mt++) {
                const int rbase = warpM * 64 + mt * 16;
                af[mt][0] = f32_to_tf32(Ab[(rbase + gid)     * AS_STRIDE + kb + tig]);
                af[mt][1] = f32_to_tf32(Ab[(rbase + gid + 8) * AS_STRIDE + kb + tig]);
                af[mt][2] = f32_to_tf32(Ab[(rbase + gid)     * AS_STRIDE + kb + tig + 4]);
                af[mt][3] = f32_to_tf32(Ab[(rbase + gid + 8) * AS_STRIDE + kb + tig + 4]);
            }
#pragma unroll
            for (int nt = 0; nt < 4; nt++) {
                const int cb = warpN * 32 + nt * 8 + gid;
                bf[nt][0] = f32_to_tf32(Bb[(kb + tig)     * BS_STRIDE + cb]);
                bf[nt][1] = f32_to_tf32(Bb[(kb + tig + 4) * BS_STRIDE + cb]);
            }
#pragma unroll
            for (int mt = 0; mt < 4; mt++)
#pragma unroll
                for (int nt = 0; nt < 4; nt++)
                    mma_tf32(acc[mt][nt][0], acc[mt][nt][1], acc[mt][nt][2], acc[mt][nt][3],
                             af[mt][0], af[mt][1], af[mt][2], af[mt][3],
                             bf[nt][0], bf[nt][1]);
        }
        __syncthreads();
    }

    // epilogue: float2 stores
#pragma unroll
    for (int mt = 0; mt < 4; mt++) {
        const int r = row0 + warpM * 64 + mt * 16 + gid;
#pragma unroll
        for (int nt = 0; nt < 4; nt++) {
            const int c = col0 + warpN * 32 + nt * 8 + tig * 2;
            *(float2*)(C + (size_t)r * N + c)       = make_float2(acc[mt][nt][0], acc[mt][nt][1]);
            *(float2*)(C + (size_t)(r + 8) * N + c) = make_float2(acc[mt][nt][2], acc[mt][nt][3]);
        }
    }
}

// ---------------- rope table: (cos,sin) for pos x freq -------------------------
__global__ void rope_table_kernel()
{
    const int idx = blockIdx.x * 256 + threadIdx.x;   // < SC_*128
    const int pos = idx >> 7;
    const int i   = idx & 127;
    const double ts  = pow(10000.0, (double)i / 128.0);
    const double ang = (double)pos / ts;
    double sn, cs;
    sincos(ang, &sn, &cs);
    g_rope[idx] = make_float2((float)cs, (float)sn);
}

// ---------------- cache merge ---------------------------------------------------
__global__ void merge_cache(const float* __restrict__ kcache,
                            const float* __restrict__ vcache,
                            const int* __restrict__ cur)
{
    const int idx = blockIdx.x * 256 + threadIdx.x;
    const int per_b = SC_ * NKV_ * HD_;
    const int b = idx / per_b;
    const int rem = idx - b * per_b;
    const int s = rem / (NKV_ * HD_);
    const int c = rem - s * (NKV_ * HD_);
    const int ci = *cur;
    const int t = s - ci;
    g_kc[idx] = kcache[idx];   // K slice overwritten later by normrope_k
    g_vc[idx] = (t >= 0 && t < T_) ? g_v[((size_t)b * T_ + t) * (NKV_ * HD_) + c]
                                   : vcache[idx];
}

// ---------------- RMSNorm + RoPE (table lookup) ---------------------------------
__global__ void normrope_kernel(const float* __restrict__ in,
                                float* __restrict__ out,
                                const float* __restrict__ scale,
                                const int* __restrict__ seg,
                                const int* __restrict__ cur,
                                int heads, int to_cache)
{
    const int bt = blockIdx.x;
    const int h  = blockIdx.y;
    const int d  = threadIdx.x;

    const float v = in[((size_t)bt * heads + h) * HD_ + d];

    float ss = v * v;
#pragma unroll
    for (int o = 16; o; o >>= 1) ss += __shfl_xor_sync(0xffffffffu, ss, o);
    __shared__ float red[8];
    __shared__ float s_ms;
    __shared__ float sh[HD_];
    const int lane = d & 31, w = d >> 5;
    if (lane == 0) red[w] = ss;
    __syncthreads();
    if (d == 0) {
        float t = 0.0f;
#pragma unroll
        for (int i = 0; i < 8; i++) t += red[i];
        s_ms = rsqrtf(t / (float)HD_ + 1e-6f);
    }
    __syncthreads();

    const float n = v * s_ms * (1.0f + scale[d]);
    sh[d] = n;
    __syncthreads();

    int pos = seg[bt];
    if (pos < 0) pos = 0;
    if (pos > SC_ - 1) pos = SC_ - 1;
    const int i = d & 127;
    const float2 cssn = g_rope[pos * 128 + i];
    const float x1 = sh[i], x2 = sh[i + 128];
    const float r = (d < 128) ? (x1 * cssn.x - x2 * cssn.y)
                              : (x2 * cssn.x + x1 * cssn.y);

    if (to_cache) {
        const int b = bt / T_, t = bt - b * T_;
        const int slot = *cur + t;
        if (slot < SC_)
            out[(((size_t)b * SC_ + slot) * heads + h) * HD_ + d] = r;
    } else {
        out[((size_t)bt * heads + h) * HD_ + d] = r;
    }
}

// ---------------- windowed flash attention ---------------------------------------
struct AttnSmem {
    float Qs[32 * 260];
    float Ks[32 * 260];
    float Vs[32 * 260];
    float Ss[32 * 33];
    float m[32], l[32], al[32];
    int   pos[32];
    int   srange[2];
};

__global__ void __launch_bounds__(256) attn_kernel(const int* __restrict__ seg)
{
    extern __shared__ char smem_raw[];
    AttnSmem& sm = *reinterpret_cast<AttnSmem*>(smem_raw);

    const int tid = threadIdx.x;
    const int q0  = blockIdx.x * 32;
    const int h   = blockIdx.y;
    const int b   = blockIdx.z;
    const int kv  = h / (NH_ / NKV_);

    const float* qbase = g_q + (((size_t)b * T_ + q0) * NH_ + h) * HD_;
    const float qscale = 0.0625f;
#pragma unroll
    for (int j = 0; j < 8; j++) {
        const int fi = tid + j * 256;
        const int r = fi >> 6, c4 = fi & 63;
        float4 v = *(const float4*)(qbase + (size_t)r * NH_ * HD_ + c4 * 4);
        float* dst = &sm.Qs[r * 260 + c4 * 4];
        dst[0] = v.x * qscale; dst[1] = v.y * qscale;
        dst[2] = v.z * qscale; dst[3] = v.w * qscale;
    }
    if (tid < 32) {
        sm.m[tid] = -1e30f;
        sm.l[tid] = 0.0f;
        sm.pos[tid] = seg[b * T_ + q0 + tid];
    }
    __syncthreads();
    if (tid == 0) {
        int mn = sm.pos[0], mx = sm.pos[0];
        for (int j = 1; j < 32; j++) { mn = min(mn, sm.pos[j]); mx = max(mx, sm.pos[j]); }
        int lo = mn - (WIN_ - 1); if (lo < 0) lo = 0;
        int hi = mx; if (hi > SC_ - 1) hi = SC_ - 1;
        sm.srange[0] = lo & ~31;
        sm.srange[1] = hi;
    }
    __syncthreads();
    const int s_lo = sm.srange[0], s_hi = sm.srange[1];

    float4 o4[8];
#pragma unroll
    for (int j = 0; j < 8; j++) o4[j] = make_float4(0.f, 0.f, 0.f, 0.f);
    const int r_acc = tid & 31;
    const int dg    = tid >> 5;

    const float* kbase = g_kc + ((size_t)b * SC_ * NKV_ + kv) * HD_;
    const float* vbase = g_vc + ((size_t)b * SC_ * NKV_ + kv) * HD_;

    for (int s0 = s_lo; s0 <= s_hi; s0 += 32) {
#pragma unroll
        for (int j = 0; j < 8; j++) {
            const int fi = tid + j * 256;
            const int r = fi >> 6, c4 = fi & 63;
            const int s = s0 + r;
            float4 kvv = make_float4(0.f,0.f,0.f,0.f), vvv = kvv;
            if (s < SC_) {
                kvv = *(const float4*)(kbase + (size_t)s * NKV_ * HD_ + c4 * 4);
                vvv = *(const float4*)(vbase + (size_t)s * NKV_ * HD_ + c4 * 4);
            }
            float* kd = &sm.Ks[r * 260 + c4 * 4];
            kd[0] = kvv.x; kd[1] = kvv.y; kd[2] = kvv.z; kd[3] = kvv.w;
            float* vd = &sm.Vs[r * 260 + c4 * 4];
            vd[0] = vvv.x; vd[1] = vvv.y; vd[2] = vvv.z; vd[3] = vvv.w;
        }
        __syncthreads();

        {
            const int qr = tid >> 3, gi = tid & 7;
            float acc[4] = {0.f, 0.f, 0.f, 0.f};
            const float* qrow = &sm.Qs[qr * 260];
            for (int d4 = 0; d4 < 64; d4++) {
                const float4 qv = *(const float4*)&qrow[d4 * 4];
#pragma unroll
                for (int i = 0; i < 4; i++) {
                    const float4 kvv = *(const float4*)&sm.Ks[(gi + 8*i) * 260 + d4 * 4];
                    acc[i] += qv.x*kvv.x + qv.y*kvv.y + qv.z*kvv.z + qv.w*kvv.w;
                }
            }
            const int qp = sm.pos[qr];
#pragma unroll
            for (int i = 0; i < 4; i++) {
                const int sj = gi + 8*i;
                const int s  = s0 + sj;
                const float sv = SOFTCAP * tanhf(acc[i] * (1.0f / SOFTCAP));
                const bool valid = (s <= qp) && (qp - s < WIN_) && (s < SC_);
                sm.Ss[qr * 33 + sj] = valid ? sv : NEGINF;
            }
        }
        __syncthreads();

        if (tid < 32) {
            const int r = tid;
            const float mo = sm.m[r];
            float mx = mo;
            for (int j = 0; j < 32; j++) mx = fmaxf(mx, sm.Ss[r * 33 + j]);
            const float a = expf(mo - mx);
            float ls = sm.l[r] * a;
            for (int j = 0; j < 32; j++) {
                const float p = expf(sm.Ss[r * 33 + j] - mx);
                sm.Ss[r * 33 + j] = p;
                ls += p;
            }
            sm.m[r] = mx; sm.l[r] = ls; sm.al[r] = a;
        }
        __syncthreads();

        {
            const float a = sm.al[r_acc];
#pragma unroll
            for (int j = 0; j < 8; j++) {
                o4[j].x *= a; o4[j].y *= a; o4[j].z *= a; o4[j].w *= a;
            }
            for (int s = 0; s < 32; s++) {
                const float p = sm.Ss[r_acc * 33 + s];
                const float4* vr = (const float4*)&sm.Vs[s * 260 + dg * 32];
#pragma unroll
                for (int j = 0; j < 8; j++) {
                    const float4 vv = vr[j];
                    o4[j].x += p * vv.x; o4[j].y += p * vv.y;
                    o4[j].z += p * vv.z; o4[j].w += p * vv.w;
                }
            }
        }
        __syncthreads();
    }

    const float linv = 1.0f / sm.l[r_acc];
    float* outp = g_attn + (((size_t)b * T_ + q0 + r_acc) * NH_ + h) * HD_ + dg * 32;
#pragma unroll
    for (int j = 0; j < 8; j++) {
        float4 v = o4[j];
        v.x *= linv; v.y *= linv; v.z *= linv; v.w *= linv;
        *(float4*)(outp + j * 4) = v;
    }
}

// ---------------- launcher --------------------------------------------------------
extern "C" void kernel_launch(void* const* d_in, const int* in_sizes, int n_in,
                              void* d_out, int out_size)
{
    const float* x      = (const float*)d_in[0];
    const int*   seg    = (const int*)  d_in[1];
    const int*   cur    = (const int*)  d_in[2];
    const float* wq     = (const float*)d_in[3];
    const float* wk     = (const float*)d_in[4];
    const float* wv     = (const float*)d_in[5];
    const float* wo     = (const float*)d_in[6];
    const float* qns    = (const float*)d_in[7];
    const float* kns    = (const float*)d_in[8];
    const float* kcache = (const float*)d_in[9];
    const float* vcache = (const float*)d_in[10];
    float* out = (float*)d_out;

    float *qp, *kp, *vp, *attnp, *kcp;
    cudaGetSymbolAddress((void**)&qp,    g_q);
    cudaGetSymbolAddress((void**)&kp,    g_k);
    cudaGetSymbolAddress((void**)&vp,    g_v);
    cudaGetSymbolAddress((void**)&attnp, g_attn);
    cudaGetSymbolAddress((void**)&kcp,   g_kc);

    const int M = B_ * T_;  // 4096

    rope_table_kernel<<<(SC_ * 128) / 256, 256>>>();

    // QKV projections (tf32 tensor cores)
    gemm_tf32<<<dim3((NH_*HD_)/128,  M/128), 256>>>(x, wq, qp, M, NH_*HD_,  D_);
    gemm_tf32<<<dim3((NKV_*HD_)/128, M/128), 256>>>(x, wk, kp, M, NKV_*HD_, D_);
    gemm_tf32<<<dim3((NKV_*HD_)/128, M/128), 256>>>(x, wv, vp, M, NKV_*HD_, D_);

    merge_cache<<<(B_*SC_*NKV_*HD_)/256, 256>>>(kcache, vcache, cur);

    normrope_kernel<<<dim3(M, NH_),  256>>>(qp, qp,  qns, seg, cur, NH_,  0);
    normrope_kernel<<<dim3(M, NKV_), 256>>>(kp, kcp, kns, seg, cur, NKV_, 1);

    cudaFuncSetAttribute(attn_kernel, cudaFuncAttributeMaxDynamicSharedMemorySize,
                         (int)sizeof(AttnSmem));
    attn_kernel<<<dim3(T_/32, NH_, B_), 256, sizeof(AttnSmem)>>>(seg);

    // output projection (tf32 tensor cores)
    gemm_tf32<<<dim3(D_/128, M/128), 256>>>(attnp, wo, out, M, D_, D_);
}

// round 4
// speedup vs baseline: 4.5525x; 1.2453x over previous
#include <cuda_runtime.h>
#include <math.h>
#include <stdint.h>

#define B_      2
#define T_      2048
#define D_      2048
#define NH_     8
#define NKV_    4
#define HD_     256
#define SC_     2048
#define WIN_    512
#define SOFTCAP 50.0f
#define NEGINF  -2.3819763e38f

// ---------------- scratch (device globals; no allocation allowed) ------------
__device__ float g_q[(size_t)B_*T_*NH_*HD_];
__device__ float g_k[(size_t)B_*T_*NKV_*HD_];
__device__ float g_v[(size_t)B_*T_*NKV_*HD_];
__device__ float g_kc[(size_t)B_*SC_*NKV_*HD_];
__device__ float g_vc[(size_t)B_*SC_*NKV_*HD_];
__device__ float g_attn[(size_t)B_*T_*NH_*HD_];
__device__ float2 g_rope[(size_t)SC_*128];

// ---------------- tf32 helpers -------------------------------------------------
__device__ __forceinline__ uint32_t f32_to_tf32(float x) {
    uint32_t y;
    asm("cvt.rna.tf32.f32 %0, %1;" : "=r"(y) : "f"(x));
    return y;
}
__device__ __forceinline__ void tf32split(float x, float& hi, float& lo) {
    hi = __uint_as_float(f32_to_tf32(x));
    lo = __uint_as_float(f32_to_tf32(x - hi));
}

__device__ __forceinline__ void mma_tf32(float& d0, float& d1, float& d2, float& d3,
                                         uint32_t a0, uint32_t a1, uint32_t a2, uint32_t a3,
                                         uint32_t b0, uint32_t b1) {
    asm volatile("mma.sync.aligned.m16n8k8.row.col.f32.tf32.tf32.f32 "
                 "{%0,%1,%2,%3}, {%4,%5,%6,%7}, {%8,%9}, {%0,%1,%2,%3};"
                 : "+f"(d0), "+f"(d1), "+f"(d2), "+f"(d3)
                 : "r"(a0), "r"(a1), "r"(a2), "r"(a3), "r"(b0), "r"(b1));
}

__device__ __forceinline__ void cpasync16(uint32_t saddr, const void* gptr) {
    asm volatile("cp.async.cg.shared.global [%0], [%1], 16;\n" :: "r"(saddr), "l"(gptr));
}
__device__ __forceinline__ void cpasync_commit() { asm volatile("cp.async.commit_group;"); }
__device__ __forceinline__ void cpasync_wait0()  { asm volatile("cp.async.wait_group 0;"); }
__device__ __forceinline__ void cpasync_wait1()  { asm volatile("cp.async.wait_group 1;"); }

// ---------------- tf32 tensor-core GEMM (unchanged from R2) --------------------
#define AS_STRIDE 20
#define BS_STRIDE 136

__global__ void __launch_bounds__(256) gemm_tf32(const float* __restrict__ A,
                                                 const float* __restrict__ W,
                                                 float* __restrict__ C,
                                                 int M, int N, int K)
{
    __shared__ float As[2][128 * AS_STRIDE];
    __shared__ float Bs[2][16 * BS_STRIDE];

    const int tid  = threadIdx.x;
    const int warp = tid >> 5;
    const int lane = tid & 31;
    const int warpM = warp >> 2;
    const int warpN = warp & 3;
    const int gid = lane >> 2;
    const int tig = lane & 3;

    const int row0 = blockIdx.y * 128;
    const int col0 = blockIdx.x * 128;

    const int a_r  = tid >> 2;
    const int a_c4 = (tid & 3) * 4;
    const int b_r  = tid >> 5;
    const int b_c4 = (tid & 31) * 4;

    uint32_t sA = (uint32_t)__cvta_generic_to_shared(&As[0][0]);
    uint32_t sB = (uint32_t)__cvta_generic_to_shared(&Bs[0][0]);
    const uint32_t sAbuf = 128 * AS_STRIDE * 4;
    const uint32_t sBbuf = 16 * BS_STRIDE * 4;

    const int ntiles = K / 16;

    auto load_tile = [&](int kt, int buf) {
        const float* ag0 = A + (size_t)(row0 + a_r) * K + kt * 16 + a_c4;
        const float* ag1 = A + (size_t)(row0 + a_r + 64) * K + kt * 16 + a_c4;
        cpasync16(sA + buf * sAbuf + (a_r * AS_STRIDE + a_c4) * 4, ag0);
        cpasync16(sA + buf * sAbuf + ((a_r + 64) * AS_STRIDE + a_c4) * 4, ag1);
        const float* bg0 = W + (size_t)(kt * 16 + b_r) * N + col0 + b_c4;
        const float* bg1 = W + (size_t)(kt * 16 + b_r + 8) * N + col0 + b_c4;
        cpasync16(sB + buf * sBbuf + (b_r * BS_STRIDE + b_c4) * 4, bg0);
        cpasync16(sB + buf * sBbuf + ((b_r + 8) * BS_STRIDE + b_c4) * 4, bg1);
    };

    float acc[4][4][4];
#pragma unroll
    for (int i = 0; i < 4; i++)
#pragma unroll
        for (int j = 0; j < 4; j++)
#pragma unroll
            for (int r = 0; r < 4; r++) acc[i][j][r] = 0.0f;

    load_tile(0, 0);
    cpasync_commit();

    for (int kt = 0; kt < ntiles; kt++) {
        const int buf = kt & 1;
        if (kt + 1 < ntiles) {
            load_tile(kt + 1, buf ^ 1);
            cpasync_commit();
            cpasync_wait1();
        } else {
            cpasync_wait0();
        }
        __syncthreads();

        const float* Ab = &As[buf][0];
        const float* Bb = &Bs[buf][0];

#pragma unroll
        for (int ks = 0; ks < 2; ks++) {
            const int kb = ks * 8;
            uint32_t af[4][4], bf[4][2];
#pragma unroll
            for (int mt = 0; mt < 4; mt++) {
                const int rbase = warpM * 64 + mt * 16;
                af[mt][0] = f32_to_tf32(Ab[(rbase + gid)     * AS_STRIDE + kb + tig]);
                af[mt][1] = f32_to_tf32(Ab[(rbase + gid + 8) * AS_STRIDE + kb + tig]);
                af[mt][2] = f32_to_tf32(Ab[(rbase + gid)     * AS_STRIDE + kb + tig + 4]);
                af[mt][3] = f32_to_tf32(Ab[(rbase + gid + 8) * AS_STRIDE + kb + tig + 4]);
            }
#pragma unroll
            for (int nt = 0; nt < 4; nt++) {
                const int cb = warpN * 32 + nt * 8 + gid;
                bf[nt][0] = f32_to_tf32(Bb[(kb + tig)     * BS_STRIDE + cb]);
                bf[nt][1] = f32_to_tf32(Bb[(kb + tig + 4) * BS_STRIDE + cb]);
            }
#pragma unroll
            for (int mt = 0; mt < 4; mt++)
#pragma unroll
                for (int nt = 0; nt < 4; nt++)
                    mma_tf32(acc[mt][nt][0], acc[mt][nt][1], acc[mt][nt][2], acc[mt][nt][3],
                             af[mt][0], af[mt][1], af[mt][2], af[mt][3],
                             bf[nt][0], bf[nt][1]);
        }
        __syncthreads();
    }

#pragma unroll
    for (int mt = 0; mt < 4; mt++) {
        const int r = row0 + warpM * 64 + mt * 16 + gid;
#pragma unroll
        for (int nt = 0; nt < 4; nt++) {
            const int c = col0 + warpN * 32 + nt * 8 + tig * 2;
            *(float2*)(C + (size_t)r * N + c)       = make_float2(acc[mt][nt][0], acc[mt][nt][1]);
            *(float2*)(C + (size_t)(r + 8) * N + c) = make_float2(acc[mt][nt][2], acc[mt][nt][3]);
        }
    }
}

// ---------------- rope table ----------------------------------------------------
__global__ void rope_table_kernel()
{
    const int idx = blockIdx.x * 256 + threadIdx.x;
    const int pos = idx >> 7;
    const int i   = idx & 127;
    const double ts  = pow(10000.0, (double)i / 128.0);
    const double ang = (double)pos / ts;
    double sn, cs;
    sincos(ang, &sn, &cs);
    g_rope[idx] = make_float2((float)cs, (float)sn);
}

// ---------------- cache merge -----------------------------------------------------
__global__ void merge_cache(const float* __restrict__ kcache,
                            const float* __restrict__ vcache,
                            const int* __restrict__ cur)
{
    const int idx = blockIdx.x * 256 + threadIdx.x;
    const int per_b = SC_ * NKV_ * HD_;
    const int b = idx / per_b;
    const int rem = idx - b * per_b;
    const int s = rem / (NKV_ * HD_);
    const int c = rem - s * (NKV_ * HD_);
    const int ci = *cur;
    const int t = s - ci;
    g_kc[idx] = kcache[idx];
    g_vc[idx] = (t >= 0 && t < T_) ? g_v[((size_t)b * T_ + t) * (NKV_ * HD_) + c]
                                   : vcache[idx];
}

// ---------------- RMSNorm + RoPE ---------------------------------------------------
__global__ void normrope_kernel(const float* __restrict__ in,
                                float* __restrict__ out,
                                const float* __restrict__ scale,
                                const int* __restrict__ seg,
                                const int* __restrict__ cur,
                                int heads, int to_cache)
{
    const int bt = blockIdx.x;
    const int h  = blockIdx.y;
    const int d  = threadIdx.x;

    const float v = in[((size_t)bt * heads + h) * HD_ + d];

    float ss = v * v;
#pragma unroll
    for (int o = 16; o; o >>= 1) ss += __shfl_xor_sync(0xffffffffu, ss, o);
    __shared__ float red[8];
    __shared__ float s_ms;
    __shared__ float sh[HD_];
    const int lane = d & 31, w = d >> 5;
    if (lane == 0) red[w] = ss;
    __syncthreads();
    if (d == 0) {
        float t = 0.0f;
#pragma unroll
        for (int i = 0; i < 8; i++) t += red[i];
        s_ms = rsqrtf(t / (float)HD_ + 1e-6f);
    }
    __syncthreads();

    const float n = v * s_ms * (1.0f + scale[d]);
    sh[d] = n;
    __syncthreads();

    int pos = seg[bt];
    if (pos < 0) pos = 0;
    if (pos > SC_ - 1) pos = SC_ - 1;
    const int i = d & 127;
    const float2 cssn = g_rope[pos * 128 + i];
    const float x1 = sh[i], x2 = sh[i + 128];
    const float r = (d < 128) ? (x1 * cssn.x - x2 * cssn.y)
                              : (x2 * cssn.x + x1 * cssn.y);

    if (to_cache) {
        const int b = bt / T_, t = bt - b * T_;
        const int slot = *cur + t;
        if (slot < SC_)
            out[(((size_t)b * SC_ + slot) * heads + h) * HD_ + d] = r;
    } else {
        out[((size_t)bt * heads + h) * HD_ + d] = r;
    }
}

// ---------------- tensor-core flash attention --------------------------------------
// Block = (b, head, 32-query tile). 256 threads = 8 warps (2M x 4N).
// S tile: 32 queries x 32 keys. QK^T: split-tf32 (3 mma). PV: single tf32.
#define QKS 260   // Q/K smem row stride
#define VSS 264   // V smem row stride
#define SSS 36    // S/P smem row stride

struct AttnSmem {
    float Qhi[32 * QKS];
    float Qlo[32 * QKS];
    float Khi[32 * QKS];
    float Klo[32 * QKS];
    float Vs [32 * VSS];
    float Ss [32 * SSS];
    float m[32], l[32], al[32];
    int   pos[32];
    int   srange[2];
};

__global__ void __launch_bounds__(256) attn_mma(const int* __restrict__ seg)
{
    extern __shared__ char smem_raw[];
    AttnSmem& sm = *reinterpret_cast<AttnSmem*>(smem_raw);

    const int tid  = threadIdx.x;
    const int warp = tid >> 5;
    const int lane = tid & 31;
    const int gid  = lane >> 2;   // 0..7
    const int tig  = lane & 3;    // 0..3
    const int warpM = warp >> 2;  // 0..1  (16 S-rows each)
    const int warpN = warp & 3;   // 0..3  (8 S-cols each / 64 O-cols each)

    const int q0 = blockIdx.x * 32;
    const int h  = blockIdx.y;
    const int b  = blockIdx.z;
    const int kvh = h / (NH_ / NKV_);

    // ---- Q load: scale, split to tf32 hi/lo ----
    const float* qbase = g_q + (((size_t)b * T_ + q0) * NH_ + h) * HD_;
    const float qscale = 0.0625f;   // 1/sqrt(256)
#pragma unroll
    for (int j = 0; j < 8; j++) {
        const int fi = tid + j * 256;        // 2048 float4 over 32x64
        const int r = fi >> 6, c4 = (fi & 63) * 4;
        float4 v = *(const float4*)(qbase + (size_t)r * NH_ * HD_ + c4);
        float hv, lv;
        tf32split(v.x * qscale, hv, lv); sm.Qhi[r*QKS+c4+0]=hv; sm.Qlo[r*QKS+c4+0]=lv;
        tf32split(v.y * qscale, hv, lv); sm.Qhi[r*QKS+c4+1]=hv; sm.Qlo[r*QKS+c4+1]=lv;
        tf32split(v.z * qscale, hv, lv); sm.Qhi[r*QKS+c4+2]=hv; sm.Qlo[r*QKS+c4+2]=lv;
        tf32split(v.w * qscale, hv, lv); sm.Qhi[r*QKS+c4+3]=hv; sm.Qlo[r*QKS+c4+3]=lv;
    }
    if (tid < 32) {
        sm.m[tid] = -1e30f;
        sm.l[tid] = 0.0f;
        sm.pos[tid] = seg[b * T_ + q0 + tid];
    }
    __syncthreads();
    if (tid == 0) {
        int mn = sm.pos[0], mx = sm.pos[0];
        for (int j = 1; j < 32; j++) { mn = min(mn, sm.pos[j]); mx = max(mx, sm.pos[j]); }
        int lo = mn - (WIN_ - 1); if (lo < 0) lo = 0;
        int hi = mx; if (hi > SC_ - 1) hi = SC_ - 1;
        sm.srange[0] = lo & ~31;
        sm.srange[1] = hi;
    }
    __syncthreads();
    const int s_lo = sm.srange[0], s_hi = sm.srange[1];

    const int arow = warpM * 16 + gid;     // local S row (this thread's frag rows: arow, arow+8)

    float o[8][4];
#pragma unroll
    for (int nf = 0; nf < 8; nf++)
#pragma unroll
        for (int r = 0; r < 4; r++) o[nf][r] = 0.0f;

    const float* kbase = g_kc + ((size_t)b * SC_ * NKV_ + kvh) * HD_;
    const float* vbase = g_vc + ((size_t)b * SC_ * NKV_ + kvh) * HD_;

    for (int s0 = s_lo; s0 <= s_hi; s0 += 32) {
        // ---- K/V tile load (split K, quantize V) ----
#pragma unroll
        for (int j = 0; j < 8; j++) {
            const int fi = tid + j * 256;
            const int r = fi >> 6, c4 = (fi & 63) * 4;
            const int s = s0 + r;
            float4 kv = make_float4(0.f,0.f,0.f,0.f), vv = kv;
            if (s < SC_) {
                kv = *(const float4*)(kbase + (size_t)s * NKV_ * HD_ + c4);
                vv = *(const float4*)(vbase + (size_t)s * NKV_ * HD_ + c4);
            }
            float hv, lv;
            tf32split(kv.x, hv, lv); sm.Khi[r*QKS+c4+0]=hv; sm.Klo[r*QKS+c4+0]=lv;
            tf32split(kv.y, hv, lv); sm.Khi[r*QKS+c4+1]=hv; sm.Klo[r*QKS+c4+1]=lv;
            tf32split(kv.z, hv, lv); sm.Khi[r*QKS+c4+2]=hv; sm.Klo[r*QKS+c4+2]=lv;
            tf32split(kv.w, hv, lv); sm.Khi[r*QKS+c4+3]=hv; sm.Klo[r*QKS+c4+3]=lv;
            sm.Vs[r*VSS+c4+0] = __uint_as_float(f32_to_tf32(vv.x));
            sm.Vs[r*VSS+c4+1] = __uint_as_float(f32_to_tf32(vv.y));
            sm.Vs[r*VSS+c4+2] = __uint_as_float(f32_to_tf32(vv.z));
            sm.Vs[r*VSS+c4+3] = __uint_as_float(f32_to_tf32(vv.w));
        }
        __syncthreads();

        // ---- QK^T (split tf32, 3 mma per k-step) ----
        float sc0 = 0.f, sc1 = 0.f, sc2 = 0.f, sc3 = 0.f;
        const int bcol = warpN * 8 + gid;
#pragma unroll 4
        for (int kb = 0; kb < HD_; kb += 8) {
            const uint32_t ah0 = __float_as_uint(sm.Qhi[(arow)    *QKS + kb + tig]);
            const uint32_t ah1 = __float_as_uint(sm.Qhi[(arow + 8)*QKS + kb + tig]);
            const uint32_t ah2 = __float_as_uint(sm.Qhi[(arow)    *QKS + kb + tig + 4]);
            const uint32_t ah3 = __float_as_uint(sm.Qhi[(arow + 8)*QKS + kb + tig + 4]);
            const uint32_t al0 = __float_as_uint(sm.Qlo[(arow)    *QKS + kb + tig]);
            const uint32_t al1 = __float_as_uint(sm.Qlo[(arow + 8)*QKS + kb + tig]);
            const uint32_t al2 = __float_as_uint(sm.Qlo[(arow)    *QKS + kb + tig + 4]);
            const uint32_t al3 = __float_as_uint(sm.Qlo[(arow + 8)*QKS + kb + tig + 4]);
            const uint32_t bh0 = __float_as_uint(sm.Khi[bcol*QKS + kb + tig]);
            const uint32_t bh1 = __float_as_uint(sm.Khi[bcol*QKS + kb + tig + 4]);
            const uint32_t bl0 = __float_as_uint(sm.Klo[bcol*QKS + kb + tig]);
            const uint32_t bl1 = __float_as_uint(sm.Klo[bcol*QKS + kb + tig + 4]);
            mma_tf32(sc0, sc1, sc2, sc3, ah0, ah1, ah2, ah3, bh0, bh1);
            mma_tf32(sc0, sc1, sc2, sc3, al0, al1, al2, al3, bh0, bh1);
            mma_tf32(sc0, sc1, sc2, sc3, ah0, ah1, ah2, ah3, bl0, bl1);
        }

        // ---- softcap + mask, write S ----
        {
            const int c0 = warpN * 8 + tig * 2;
            const int sa = s0 + c0, sb2 = s0 + c0 + 1;
            const int qp0 = sm.pos[arow], qp1 = sm.pos[arow + 8];
            const float v0 = SOFTCAP * tanhf(sc0 * (1.0f / SOFTCAP));
            const float v1 = SOFTCAP * tanhf(sc1 * (1.0f / SOFTCAP));
            const float v2 = SOFTCAP * tanhf(sc2 * (1.0f / SOFTCAP));
            const float v3 = SOFTCAP * tanhf(sc3 * (1.0f / SOFTCAP));
            sm.Ss[(arow)    *SSS + c0    ] = (sa  <= qp0 && qp0 - sa  < WIN_ && sa  < SC_) ? v0 : NEGINF;
            sm.Ss[(arow)    *SSS + c0 + 1] = (sb2 <= qp0 && qp0 - sb2 < WIN_ && sb2 < SC_) ? v1 : NEGINF;
            sm.Ss[(arow + 8)*SSS + c0    ] = (sa  <= qp1 && qp1 - sa  < WIN_ && sa  < SC_) ? v2 : NEGINF;
            sm.Ss[(arow + 8)*SSS + c0 + 1] = (sb2 <= qp1 && qp1 - sb2 < WIN_ && sb2 < SC_) ? v3 : NEGINF;
        }
        __syncthreads();

        // ---- online softmax: 8 threads/row, 4 keys each ----
        {
            const int r = tid >> 3, sub = tid & 7;
            float* srow = &sm.Ss[r * SSS + sub * 4];
            float mx = fmaxf(fmaxf(srow[0], srow[1]), fmaxf(srow[2], srow[3]));
#pragma unroll
            for (int off = 1; off < 8; off <<= 1)
                mx = fmaxf(mx, __shfl_xor_sync(0xffffffffu, mx, off));
            const float mo = sm.m[r];
            const float mn = fmaxf(mo, mx);
            const float a  = expf(mo - mn);
            float ls = 0.0f;
#pragma unroll
            for (int i = 0; i < 4; i++) {
                const float p = expf(srow[i] - mn);
                srow[i] = __uint_as_float(f32_to_tf32(p));
                ls += p;
            }
#pragma unroll
            for (int off = 1; off < 8; off <<= 1)
                ls += __shfl_xor_sync(0xffffffffu, ls, off);
            if (sub == 0) {
                sm.m[r] = mn;
                sm.l[r] = sm.l[r] * a + ls;
                sm.al[r] = a;
            }
        }
        __syncthreads();

        // ---- rescale O, then P @ V (single tf32) ----
        {
            const float a0 = sm.al[arow], a1 = sm.al[arow + 8];
#pragma unroll
            for (int nf = 0; nf < 8; nf++) {
                o[nf][0] *= a0; o[nf][1] *= a0;
                o[nf][2] *= a1; o[nf][3] *= a1;
            }
#pragma unroll
            for (int kb = 0; kb < 32; kb += 8) {
                const uint32_t pa0 = __float_as_uint(sm.Ss[(arow)    *SSS + kb + tig]);
                const uint32_t pa1 = __float_as_uint(sm.Ss[(arow + 8)*SSS + kb + tig]);
                const uint32_t pa2 = __float_as_uint(sm.Ss[(arow)    *SSS + kb + tig + 4]);
                const uint32_t pa3 = __float_as_uint(sm.Ss[(arow + 8)*SSS + kb + tig + 4]);
#pragma unroll
                for (int nf = 0; nf < 8; nf++) {
                    const int col = warpN * 64 + nf * 8 + gid;
                    const uint32_t b0 = __float_as_uint(sm.Vs[(kb + tig)    *VSS + col]);
                    const uint32_t b1 = __float_as_uint(sm.Vs[(kb + tig + 4)*VSS + col]);
                    mma_tf32(o[nf][0], o[nf][1], o[nf][2], o[nf][3],
                             pa0, pa1, pa2, pa3, b0, b1);
                }
            }
        }
        __syncthreads();
    }

    // ---- epilogue: O / l ----
    const float li0 = 1.0f / sm.l[arow];
    const float li1 = 1.0f / sm.l[arow + 8];
    const int row0g = q0 + arow;
#pragma unroll
    for (int nf = 0; nf < 8; nf++) {
        const int col = warpN * 64 + nf * 8 + tig * 2;
        float* p0 = g_attn + (((size_t)b * T_ + row0g)     * NH_ + h) * HD_ + col;
        float* p1 = g_attn + (((size_t)b * T_ + row0g + 8) * NH_ + h) * HD_ + col;
        *(float2*)p0 = make_float2(o[nf][0] * li0, o[nf][1] * li0);
        *(float2*)p1 = make_float2(o[nf][2] * li1, o[nf][3] * li1);
    }
}

// ---------------- launcher ------------------------------------------------------
extern "C" void kernel_launch(void* const* d_in, const int* in_sizes, int n_in,
                              void* d_out, int out_size)
{
    const float* x      = (const float*)d_in[0];
    const int*   seg    = (const int*)  d_in[1];
    const int*   cur    = (const int*)  d_in[2];
    const float* wq     = (const float*)d_in[3];
    const float* wk     = (const float*)d_in[4];
    const float* wv     = (const float*)d_in[5];
    const float* wo     = (const float*)d_in[6];
    const float* qns    = (const float*)d_in[7];
    const float* kns    = (const float*)d_in[8];
    const float* kcache = (const float*)d_in[9];
    const float* vcache = (const float*)d_in[10];
    float* out = (float*)d_out;

    float *qp, *kp, *vp, *attnp, *kcp;
    cudaGetSymbolAddress((void**)&qp,    g_q);
    cudaGetSymbolAddress((void**)&kp,    g_k);
    cudaGetSymbolAddress((void**)&vp,    g_v);
    cudaGetSymbolAddress((void**)&attnp, g_attn);
    cudaGetSymbolAddress((void**)&kcp,   g_kc);

    const int M = B_ * T_;

    rope_table_kernel<<<(SC_ * 128) / 256, 256>>>();

    gemm_tf32<<<dim3((NH_*HD_)/128,  M/128), 256>>>(x, wq, qp, M, NH_*HD_,  D_);
    gemm_tf32<<<dim3((NKV_*HD_)/128, M/128), 256>>>(x, wk, kp, M, NKV_*HD_, D_);
    gemm_tf32<<<dim3((NKV_*HD_)/128, M/128), 256>>>(x, wv, vp, M, NKV_*HD_, D_);

    merge_cache<<<(B_*SC_*NKV_*HD_)/256, 256>>>(kcache, vcache, cur);

    normrope_kernel<<<dim3(M, NH_),  256>>>(qp, qp,  qns, seg, cur, NH_,  0);
    normrope_kernel<<<dim3(M, NKV_), 256>>>(kp, kcp, kns, seg, cur, NKV_, 1);

    cudaFuncSetAttribute(attn_mma, cudaFuncAttributeMaxDynamicSharedMemorySize,
                         (int)sizeof(AttnSmem));
    attn_mma<<<dim3(T_/32, NH_, B_), 256, sizeof(AttnSmem)>>>(seg);

    gemm_tf32<<<dim3(D_/128, M/128), 256>>>(attnp, wo, out, M, D_, D_);
}